// round 9
// baseline (speedup 1.0000x reference)
#include <cuda_runtime.h>
#include <cuda_bf16.h>

// One-hop neighbor sampling with replacement (EdgeSampler), float32 output.
// Geometry: NUM_NODES=1e6, B=256, R=512, S=16 -> 131072 seeds, SEC=2097152.
// Output layout (validated rel_err=0): float32 [src | tgt | valid], SEC each.
//
// R9: 16 threads per seed, 1 sample per thread (2,097,152 threads).
//  - warp covers 2 seeds -> gather LDG touches ~2 cache lines (vs ~10 before)
//  - seed/rowp loads are 16-lane broadcasts
//  - 4x more independent latency chains resident (65536 warps, ~12 regs)
// Attacks the latency bound that kept R6/R7/R8 pinned at ~12us ncu.

#define N_SEEDS   131072
#define SEC       (N_SEEDS * 16)      // 2097152 floats per section = total threads

__global__ __launch_bounds__(256) void edge_sampler_kernel(
    const int*   __restrict__ seeds,
    const int*   __restrict__ rowp,
    const int*   __restrict__ col,
    const float* __restrict__ rnd,      // [SEC]
    float* __restrict__ out_src,        // [SEC]
    float* __restrict__ out_tgt,        // [SEC]
    float* __restrict__ out_val,        // [SEC]
    int row_max_idx)
{
    const unsigned u = blockIdx.x * 256u + threadIdx.x;   // < SEC by grid size
    const unsigned t = u >> 4;                            // seed index

    // Stage 1: seed id (16-lane broadcast within the warp)
    const int sid = __ldg(&seeds[t]);
    const int c   = min(max(sid, 0), row_max_idx);

    // Stage 2: row_ptr pair (2 distinct addrs/warp) + uniform (coalesced)
    const int   s = __ldg(&rowp[c]);
    const int   e = __ldg(&rowp[c + 1]);
    const float r = __ldg(&rnd[u]);

    const int  d  = e - s;
    const bool vb = (d > 0);

    // idx = (int)(r*deg) >= 0 always; clamp high; pos=0 for deg==0
    // (reference also gathers col[0] for invalid slots).
    const int idx = min((int)(r * (float)d), max(d - 1, 0));
    const int pos = vb ? s + idx : 0;

    // Stage 3: single gather; ~2 lines per warp-instruction.
    const float g = (float)__ldg(&col[pos]);

    // Coalesced scalar stores (128B per warp per section).
    out_src[u] = (float)sid;
    out_tgt[u] = g;
    out_val[u] = vb ? 1.0f : 0.0f;
}

extern "C" void kernel_launch(void* const* d_in, const int* in_sizes, int n_in,
                              void* d_out, int out_size)
{
    // ---- Bind inputs by size ratios (order- and unit-invariant) ----
    int idx_seed = 0;
    for (int i = 1; i < n_in; i++)
        if (in_sizes[i] < in_sizes[idx_seed]) idx_seed = i;

    int idx_col = 0;
    for (int i = 1; i < n_in; i++)
        if (in_sizes[i] > in_sizes[idx_col]) idx_col = i;

    int idx_rand = -1;
    for (int i = 0; i < n_in; i++) {
        if (i != idx_seed && i != idx_col &&
            (long long)in_sizes[i] == 16LL * (long long)in_sizes[idx_seed]) {
            idx_rand = i; break;
        }
    }
    int idx_row = -1;
    for (int i = 0; i < n_in; i++)
        if (i != idx_seed && i != idx_col && i != idx_rand) { idx_row = i; break; }
    if (idx_rand < 0) idx_rand = idx_row;

    const int*   seeds = (const int*)d_in[idx_seed];
    const int*   rowp  = (const int*)d_in[idx_row];
    const int*   col   = (const int*)d_in[idx_col];
    const float* rnd   = (const float*)d_in[idx_rand];

    int row_max_idx = in_sizes[idx_row] - 2;
    if (row_max_idx < 0) row_max_idx = 0;

    float* out = (float*)d_out;
    float* out_src = out;
    float* out_tgt = out + SEC;
    float* out_val = out + 2 * SEC;

    const int threads = 256;
    const int blocks  = SEC / threads;    // 8192
    edge_sampler_kernel<<<blocks, threads>>>(
        seeds, rowp, col, rnd, out_src, out_tgt, out_val, row_max_idx);
}